// round 9
// baseline (speedup 1.0000x reference)
#include <cuda_runtime.h>
#include <cuda_fp16.h>
#include <cstdint>

#define KDIM 1024
#define IDIM 64
#define ODIM 1024
#define THREADS 256
#define KC 32                  // fp32 k per chunk
#define NCHUNK (KDIM / KC)     // 32

#define ROWB 80                // fp16 tile row: 64B data + 16B pad (conflict-free LDSM)
#define TILE_B (128 * ROWB)    // 10240
#define BUF_SZ (2 * TILE_B)    // 20480: AH, BH
#define T_AH 0
#define T_BH TILE_B
#define SMEM_DYN (2 * BUF_SZ)  // 40960

static __device__ __forceinline__ uint32_t smem_u32(const void* p) {
    uint32_t a;
    asm("{ .reg .u64 t; cvta.to.shared.u64 t, %1; cvt.u32.u64 %0, t; }"
        : "=r"(a) : "l"(p));
    return a;
}

static __device__ __forceinline__ void ldm_x4(uint32_t* r, uint32_t addr) {
    asm volatile(
        "ldmatrix.sync.aligned.m8n8.x4.shared.b16 {%0,%1,%2,%3}, [%4];"
        : "=r"(r[0]), "=r"(r[1]), "=r"(r[2]), "=r"(r[3]) : "r"(addr));
}

static __device__ __forceinline__ void mma_f16(float* d, const uint32_t* a,
                                               const uint32_t* b) {
    asm volatile(
        "mma.sync.aligned.m16n8k16.row.col.f32.f16.f16.f32 "
        "{%0,%1,%2,%3}, {%4,%5,%6,%7}, {%8,%9}, {%0,%1,%2,%3};"
        : "+f"(d[0]), "+f"(d[1]), "+f"(d[2]), "+f"(d[3])
        : "r"(a[0]), "r"(a[1]), "r"(a[2]), "r"(a[3]), "r"(b[0]), "r"(b[1]));
}

static __device__ __forceinline__ uint2 pack_hi4(const float4 v) {
    __half h0 = __float2half_rn(v.x), h1 = __float2half_rn(v.y);
    __half h2 = __float2half_rn(v.z), h3 = __float2half_rn(v.w);
    uint2 r;
    r.x = (uint32_t)__half_as_ushort(h0) | ((uint32_t)__half_as_ushort(h1) << 16);
    r.y = (uint32_t)__half_as_ushort(h2) | ((uint32_t)__half_as_ushort(h3) << 16);
    return r;
}

// Per-thread tile piece: 4 float4 at f = tid + it*256; row = f>>3, c4 = f&7.
#define LDG4(dst, gbase)                                                        \
    do {                                                                        \
        _Pragma("unroll") for (int it_ = 0; it_ < 4; ++it_) {                   \
            int f_ = threadIdx.x + it_ * THREADS;                               \
            int row_ = f_ >> 3, c4_ = f_ & 7;                                   \
            (dst)[it_] = *reinterpret_cast<const float4*>(                      \
                (gbase) + (size_t)row_ * 65536 + c4_ * 4);                      \
        }                                                                       \
    } while (0)

#define STS4(src, sm, toff)                                                     \
    do {                                                                        \
        _Pragma("unroll") for (int it_ = 0; it_ < 4; ++it_) {                   \
            int f_ = threadIdx.x + it_ * THREADS;                               \
            int row_ = f_ >> 3, c4_ = f_ & 7;                                   \
            *reinterpret_cast<uint2*>((sm) + (toff) + row_ * ROWB + c4_ * 8) =  \
                pack_hi4((src)[it_]);                                           \
        }                                                                       \
    } while (0)

__global__ void __launch_bounds__(THREADS, 2)
fl_kernel(const float* __restrict__ x, const float* __restrict__ w,
          const float* __restrict__ bias, float* __restrict__ out) {
    extern __shared__ char sm[];
    const uint32_t sbase = smem_u32(sm);
    const int tid = threadIdx.x;
    const int wid = tid >> 5;
    const int lid = tid & 31;
    const int warp_m = wid >> 2;   // 0..1 : 64 M rows each
    const int warp_n = wid & 3;    // 0..3 : 32 N cols each
    const int otile = blockIdx.x;  // 0..7
    const int i_idx = blockIdx.y;  // 0..63

    const float* xa = x + (size_t)i_idx * KDIM;
    const float* wa = w + ((size_t)otile * 128) * (IDIM * KDIM) + (size_t)i_idx * KDIM;

    float acc[4][4][4];
#pragma unroll
    for (int a = 0; a < 4; ++a)
#pragma unroll
        for (int b = 0; b < 4; ++b)
#pragma unroll
            for (int c = 0; c < 4; ++c) acc[a][b][c] = 0.0f;

    const uint32_t a_row = (uint32_t)(warp_m * 64 + (lid & 15));
    const uint32_t a_cb = (uint32_t)((lid >> 4) * 16);
    const uint32_t b_row = (uint32_t)(warp_n * 32 + ((lid >> 4) << 3) + (lid & 7));
    const uint32_t b_cb = (uint32_t)(((lid >> 3) & 1) * 16);

    // Prologue: load + convert chunk 0 into buf 0.
    {
        float4 pa[4], pb[4];
        LDG4(pa, xa);
        LDG4(pb, wa);
        STS4(pa, sm, 0 + T_AH);
        STS4(pb, sm, 0 + T_BH);
    }
    __syncthreads();

    float4 pf[4];
    for (int ch = 0; ch < NCHUNK; ++ch) {
        const uint32_t buf = sbase + (uint32_t)((ch & 1) * BUF_SZ);
        const uint32_t nbuf = (uint32_t)(((ch + 1) & 1) * BUF_SZ);
        const bool hasnext = (ch + 1 < NCHUNK);

        // Phase 1: prefetch A of ch+1, MMA ks=0, then cvt+STS A.
        if (hasnext) LDG4(pf, xa + (ch + 1) * KC);
        {
            uint32_t ah[4][4], bh[2][4];
#pragma unroll
            for (int mt = 0; mt < 4; ++mt)
                ldm_x4(ah[mt], buf + T_AH + (a_row + mt * 16) * ROWB + a_cb);
#pragma unroll
            for (int bt = 0; bt < 2; ++bt)
                ldm_x4(bh[bt], buf + T_BH + (b_row + bt * 16) * ROWB + b_cb);
#pragma unroll
            for (int mt = 0; mt < 4; ++mt)
#pragma unroll
                for (int nt = 0; nt < 4; ++nt)
                    mma_f16(acc[mt][nt], ah[mt], &bh[nt >> 1][(nt & 1) * 2]);
        }
        if (hasnext) STS4(pf, sm, nbuf + T_AH);

        // Phase 2: prefetch B of ch+1, MMA ks=1, then cvt+STS B.
        if (hasnext) LDG4(pf, wa + (ch + 1) * KC);
        {
            uint32_t ah[4][4], bh[2][4];
#pragma unroll
            for (int mt = 0; mt < 4; ++mt)
                ldm_x4(ah[mt], buf + T_AH + (a_row + mt * 16) * ROWB + 32 + a_cb);
#pragma unroll
            for (int bt = 0; bt < 2; ++bt)
                ldm_x4(bh[bt], buf + T_BH + (b_row + bt * 16) * ROWB + 32 + b_cb);
#pragma unroll
            for (int mt = 0; mt < 4; ++mt)
#pragma unroll
                for (int nt = 0; nt < 4; ++nt)
                    mma_f16(acc[mt][nt], ah[mt], &bh[nt >> 1][(nt & 1) * 2]);
        }
        if (hasnext) STS4(pf, sm, nbuf + T_BH);

        __syncthreads();
    }

    // Epilogue: add bias, store. out[b][o][i] = b*65536 + o*64 + i
    const float* bp = bias + (size_t)(otile * 128) * IDIM + i_idx;
    float bv[4][2];
#pragma unroll
    for (int nt = 0; nt < 4; ++nt) {
        int n_l = warp_n * 32 + nt * 8 + 2 * (lid & 3);
        bv[nt][0] = bp[(size_t)n_l * IDIM];
        bv[nt][1] = bp[(size_t)(n_l + 1) * IDIM];
    }
#pragma unroll
    for (int mt = 0; mt < 4; ++mt) {
        int m0 = warp_m * 64 + mt * 16 + (lid >> 2);
#pragma unroll
        for (int nt = 0; nt < 4; ++nt) {
            int n_l = warp_n * 32 + nt * 8 + 2 * (lid & 3);
            float* o0 = out + (size_t)m0 * (ODIM * IDIM) +
                        (size_t)(otile * 128 + n_l) * IDIM + i_idx;
            o0[0] = acc[mt][nt][0] + bv[nt][0];
            o0[IDIM] = acc[mt][nt][1] + bv[nt][1];
            float* o8 = o0 + (size_t)8 * (ODIM * IDIM);
            o8[0] = acc[mt][nt][2] + bv[nt][0];
            o8[IDIM] = acc[mt][nt][3] + bv[nt][1];
        }
    }
}

extern "C" void kernel_launch(void* const* d_in, const int* in_sizes, int n_in,
                              void* d_out, int out_size) {
    (void)in_sizes; (void)n_in; (void)out_size;
    const float* x = (const float*)d_in[0];
    const float* w = (const float*)d_in[1];
    const float* bias = (const float*)d_in[2];
    float* out = (float*)d_out;

    cudaFuncSetAttribute(fl_kernel, cudaFuncAttributeMaxDynamicSharedMemorySize,
                         SMEM_DYN);
    fl_kernel<<<dim3(ODIM / 128, IDIM), THREADS, SMEM_DYN>>>(x, w, bias, out);
}

// round 10
// speedup vs baseline: 1.2489x; 1.2489x over previous
#include <cuda_runtime.h>
#include <cuda_fp16.h>
#include <cstdint>

#define KDIM 1024
#define IDIM 64
#define ODIM 1024
#define THREADS 256
#define KC 64                  // k per chunk
#define NCHUNK (KDIM / KC)     // 16

// fp16 tiles: 128 rows x 128B (64 fp16), XOR-swizzled, no padding
#define SWZ(off) ((uint32_t)(off) ^ ((((uint32_t)(off)) >> 3) & 0x70))
#define TILE16 16384           // one fp16 tile (A or B)

#define OFF_A0 0
#define OFF_A1 16384
#define OFF_B0 32768
#define OFF_B1 49152
#define OFF_STG 65536          // B fp32 stage: 128 x 64 fp32 = 32 KB
#define SMEM_DYN (OFF_STG + 32768)   // 98304 = 96 KB -> 2 CTAs/SM

// Pre-converted x, tiled: tile (i, ch) = 16 KB at ((i*16+ch)*16384),
// inside: swizzled [b(128) x 64 fp16] rows of 128B.
__device__ unsigned char g_xh[64 * 16 * 16384];

static __device__ __forceinline__ uint32_t smem_u32(const void* p) {
    uint32_t a;
    asm("{ .reg .u64 t; cvta.to.shared.u64 t, %1; cvt.u32.u64 %0, t; }"
        : "=r"(a) : "l"(p));
    return a;
}

static __device__ __forceinline__ void ldm_x4(uint32_t* r, uint32_t addr) {
    asm volatile(
        "ldmatrix.sync.aligned.m8n8.x4.shared.b16 {%0,%1,%2,%3}, [%4];"
        : "=r"(r[0]), "=r"(r[1]), "=r"(r[2]), "=r"(r[3]) : "r"(addr));
}

static __device__ __forceinline__ void mma_f16(float* d, const uint32_t* a,
                                               const uint32_t* b) {
    asm volatile(
        "mma.sync.aligned.m16n8k16.row.col.f32.f16.f16.f32 "
        "{%0,%1,%2,%3}, {%4,%5,%6,%7}, {%8,%9}, {%0,%1,%2,%3};"
        : "+f"(d[0]), "+f"(d[1]), "+f"(d[2]), "+f"(d[3])
        : "r"(a[0]), "r"(a[1]), "r"(a[2]), "r"(a[3]), "r"(b[0]), "r"(b[1]));
}

static __device__ __forceinline__ void cp16(uint32_t saddr, const void* gaddr) {
    asm volatile("cp.async.cg.shared.global [%0], [%1], 16;"
                 :: "r"(saddr), "l"(gaddr));
}

static __device__ __forceinline__ uint2 pack_hi4(const float4 v) {
    __half h0 = __float2half_rn(v.x), h1 = __float2half_rn(v.y);
    __half h2 = __float2half_rn(v.z), h3 = __float2half_rn(v.w);
    uint2 r;
    r.x = (uint32_t)__half_as_ushort(h0) | ((uint32_t)__half_as_ushort(h1) << 16);
    r.y = (uint32_t)__half_as_ushort(h2) | ((uint32_t)__half_as_ushort(h3) << 16);
    return r;
}

// ───────────── pre-pass: x fp32 -> swizzled fp16 tiles ─────────────
__global__ void __launch_bounds__(THREADS)
cvt_x_kernel(const float* __restrict__ x) {
    const int i = blockIdx.x;    // 0..63
    const int ch = blockIdx.y;   // 0..15
    unsigned char* tile = g_xh + ((size_t)i * NCHUNK + ch) * TILE16;
    const float* src = x + (size_t)i * KDIM + ch * KC;
#pragma unroll
    for (int it = 0; it < 8; ++it) {
        int g = threadIdx.x + it * THREADS;   // 8B fp16 granule, 0..2047
        int b = g >> 4;
        int c4 = g & 15;
        const float4 v = *reinterpret_cast<const float4*>(
            src + (size_t)b * (IDIM * KDIM) + c4 * 4);
        *reinterpret_cast<uint2*>(tile + SWZ(b * 128 + c4 * 8)) = pack_hi4(v);
    }
}

// ───────────── main GEMM ─────────────

// cp.async one A fp16 tile (16 KB, already swizzled in gmem) into smem.
static __device__ __forceinline__ void stage_a(uint32_t dst,
                                               const unsigned char* tile) {
#pragma unroll
    for (int it = 0; it < 4; ++it) {
        int g = threadIdx.x + it * THREADS;   // 16B granule, 0..1023
        cp16(dst + (uint32_t)(g * 16), tile + (size_t)g * 16);
    }
}

// cp.async one B fp32 chunk [128 x 64] into the stage (self-consumed layout).
static __device__ __forceinline__ void stage_b(uint32_t stg,
                                               const float* __restrict__ gb) {
#pragma unroll
    for (int it = 0; it < 8; ++it) {
        int f = threadIdx.x + it * THREADS;   // float4 idx 0..2047
        int row = f >> 4;
        int c4 = f & 15;
        cp16(stg + (uint32_t)(f * 16), gb + (size_t)row * 65536 + c4 * 4);
    }
}

// Convert own staged B fp32 -> swizzled fp16 tile.
static __device__ __forceinline__ void convert_b(char* sm, uint32_t buf_off) {
#pragma unroll
    for (int it = 0; it < 8; ++it) {
        int f = threadIdx.x + it * THREADS;
        int row = f >> 4;
        int c4 = f & 15;
        const float4 v = *reinterpret_cast<const float4*>(sm + OFF_STG + f * 16);
        *reinterpret_cast<uint2*>(sm + buf_off + SWZ(row * 128 + c4 * 8)) =
            pack_hi4(v);
    }
}

__global__ void __launch_bounds__(THREADS, 2)
fl_kernel(const float* __restrict__ w, const float* __restrict__ bias,
          float* __restrict__ out) {
    extern __shared__ char sm[];
    const uint32_t sbase = smem_u32(sm);
    const int tid = threadIdx.x;
    const int wid = tid >> 5;
    const int lid = tid & 31;
    const int warp_m = wid >> 2;   // 0..1 : 64 M rows each
    const int warp_n = wid & 3;    // 0..3 : 32 N cols each
    const int otile = blockIdx.x;  // 0..7
    const int i_idx = blockIdx.y;  // 0..63

    const unsigned char* xtiles = g_xh + (size_t)i_idx * NCHUNK * TILE16;
    const float* wa = w + ((size_t)otile * 128) * (IDIM * KDIM) + (size_t)i_idx * KDIM;

    float acc[4][4][4];
#pragma unroll
    for (int a = 0; a < 4; ++a)
#pragma unroll
        for (int b = 0; b < 4; ++b)
#pragma unroll
            for (int c = 0; c < 4; ++c) acc[a][b][c] = 0.0f;

    const uint32_t a_row = (uint32_t)(warp_m * 64 + (lid & 15));
    const uint32_t a_cb = (uint32_t)((lid >> 4) * 16);
    const uint32_t b_row = (uint32_t)(warp_n * 32 + ((lid >> 4) << 3) + (lid & 7));
    const uint32_t b_cb = (uint32_t)(((lid >> 3) & 1) * 16);

    // Prologue: chunk 0 -> bufs 0.
    stage_a(sbase + OFF_A0, xtiles);
    stage_b(sbase + OFF_STG, wa);
    asm volatile("cp.async.commit_group;" ::: "memory");
    asm volatile("cp.async.wait_group 0;" ::: "memory");
    convert_b(sm, OFF_B0);
    __syncthreads();

    for (int ch = 0; ch < NCHUNK; ++ch) {
        const uint32_t abuf = sbase + (uint32_t)((ch & 1) ? OFF_A1 : OFF_A0);
        const uint32_t bbuf = sbase + (uint32_t)((ch & 1) ? OFF_B1 : OFF_B0);
        const bool hasnext = (ch + 1 < NCHUNK);

        // Prefetch chunk ch+1: A fp16 tile + B fp32 stage (stage self-consumed
        // by this thread's convert at the bottom of this iteration).
        if (hasnext) {
            stage_a(sbase + ((ch & 1) ? OFF_A0 : OFF_A1),
                    xtiles + (size_t)(ch + 1) * TILE16);
            stage_b(sbase + OFF_STG, wa + (ch + 1) * KC);
        }
        asm volatile("cp.async.commit_group;" ::: "memory");

        // MMA: 4 K=16 steps on current bufs
#pragma unroll
        for (int ks = 0; ks < 4; ++ks) {
            uint32_t ah[4][4], bh[2][4];
#pragma unroll
            for (int mt = 0; mt < 4; ++mt)
                ldm_x4(ah[mt], abuf +
                       SWZ((a_row + mt * 16) * 128 + ks * 32 + a_cb));
#pragma unroll
            for (int bt = 0; bt < 2; ++bt)
                ldm_x4(bh[bt], bbuf +
                       SWZ((b_row + bt * 16) * 128 + ks * 32 + b_cb));
#pragma unroll
            for (int mt = 0; mt < 4; ++mt)
#pragma unroll
                for (int nt = 0; nt < 4; ++nt)
                    mma_f16(acc[mt][nt], ah[mt], &bh[nt >> 1][(nt & 1) * 2]);
        }

        // Land prefetch, convert B(ch+1) into the other fp16 buffer.
        asm volatile("cp.async.wait_group 0;" ::: "memory");
        if (hasnext) {
            convert_b(sm, (uint32_t)((ch & 1) ? OFF_B0 : OFF_B1));
        }
        __syncthreads();
    }

    // Epilogue: add bias, store. out[b][o][i] = b*65536 + o*64 + i
    const float* bp = bias + (size_t)(otile * 128) * IDIM + i_idx;
    float bv[4][2];
#pragma unroll
    for (int nt = 0; nt < 4; ++nt) {
        int n_l = warp_n * 32 + nt * 8 + 2 * (lid & 3);
        bv[nt][0] = bp[(size_t)n_l * IDIM];
        bv[nt][1] = bp[(size_t)(n_l + 1) * IDIM];
    }
#pragma unroll
    for (int mt = 0; mt < 4; ++mt) {
        int m0 = warp_m * 64 + mt * 16 + (lid >> 2);
#pragma unroll
        for (int nt = 0; nt < 4; ++nt) {
            int n_l = warp_n * 32 + nt * 8 + 2 * (lid & 3);
            float* o0 = out + (size_t)m0 * (ODIM * IDIM) +
                        (size_t)(otile * 128 + n_l) * IDIM + i_idx;
            o0[0] = acc[mt][nt][0] + bv[nt][0];
            o0[IDIM] = acc[mt][nt][1] + bv[nt][1];
            float* o8 = o0 + (size_t)8 * (ODIM * IDIM);
            o8[0] = acc[mt][nt][2] + bv[nt][0];
            o8[IDIM] = acc[mt][nt][3] + bv[nt][1];
        }
    }
}

extern "C" void kernel_launch(void* const* d_in, const int* in_sizes, int n_in,
                              void* d_out, int out_size) {
    (void)in_sizes; (void)n_in; (void)out_size;
    const float* x = (const float*)d_in[0];
    const float* w = (const float*)d_in[1];
    const float* bias = (const float*)d_in[2];
    float* out = (float*)d_out;

    cvt_x_kernel<<<dim3(IDIM, NCHUNK), THREADS>>>(x);

    cudaFuncSetAttribute(fl_kernel, cudaFuncAttributeMaxDynamicSharedMemorySize,
                         SMEM_DYN);
    fl_kernel<<<dim3(ODIM / 128, IDIM), THREADS, SMEM_DYN>>>(w, bias, out);
}

// round 11
// speedup vs baseline: 1.3046x; 1.0446x over previous
#include <cuda_runtime.h>
#include <cuda_fp16.h>
#include <cstdint>

#define KDIM 1024
#define IDIM 64
#define ODIM 1024
#define THREADS 256
#define KC 32                   // k per chunk
#define NCHUNK (KDIM / KC)      // 32

// 64B-row tiles, SW64 XOR swizzle (conflict-free for ldmatrix phases)
#define SWZ64(o) ((uint32_t)(o) ^ ((((uint32_t)(o)) >> 3) & 0x30))
#define TILE_A 8192             // A fp16 tile: 128 x 32 fp16
#define TILE_B16 8192           // B fp16 tile: 128 x 32 fp16
#define BSTG_SZ 16384           // B fp32 stage: 128 x 32 fp32

#define OFF_A 0                         // 3 buffers: +0, +8192, +16384
#define OFF_B16 (3 * TILE_A)            // 24576: 2 buffers
#define OFF_STG (OFF_B16 + 2 * TILE_B16)  // 40960: 2 buffers
#define SMEM_DYN (OFF_STG + 2 * BSTG_SZ)  // 73728 = 72KB -> 2 CTAs/SM

// Pre-converted x: tile (i, ch) = 8 KB at ((i*32+ch)*8192); swizzled
// [b(128) x 32 fp16] rows of 64B.
__device__ unsigned char g_xh[64 * 32 * 8192];

static __device__ __forceinline__ uint32_t smem_u32(const void* p) {
    uint32_t a;
    asm("{ .reg .u64 t; cvta.to.shared.u64 t, %1; cvt.u32.u64 %0, t; }"
        : "=r"(a) : "l"(p));
    return a;
}

static __device__ __forceinline__ void ldm_x4(uint32_t* r, uint32_t addr) {
    asm volatile(
        "ldmatrix.sync.aligned.m8n8.x4.shared.b16 {%0,%1,%2,%3}, [%4];"
        : "=r"(r[0]), "=r"(r[1]), "=r"(r[2]), "=r"(r[3]) : "r"(addr));
}

static __device__ __forceinline__ void mma_f16(float* d, const uint32_t* a,
                                               const uint32_t* b) {
    asm volatile(
        "mma.sync.aligned.m16n8k16.row.col.f32.f16.f16.f32 "
        "{%0,%1,%2,%3}, {%4,%5,%6,%7}, {%8,%9}, {%0,%1,%2,%3};"
        : "+f"(d[0]), "+f"(d[1]), "+f"(d[2]), "+f"(d[3])
        : "r"(a[0]), "r"(a[1]), "r"(a[2]), "r"(a[3]), "r"(b[0]), "r"(b[1]));
}

static __device__ __forceinline__ void cp16(uint32_t saddr, const void* gaddr) {
    asm volatile("cp.async.cg.shared.global [%0], [%1], 16;"
                 :: "r"(saddr), "l"(gaddr));
}

static __device__ __forceinline__ uint2 pack_hi4(const float4 v) {
    __half h0 = __float2half_rn(v.x), h1 = __float2half_rn(v.y);
    __half h2 = __float2half_rn(v.z), h3 = __float2half_rn(v.w);
    uint2 r;
    r.x = (uint32_t)__half_as_ushort(h0) | ((uint32_t)__half_as_ushort(h1) << 16);
    r.y = (uint32_t)__half_as_ushort(h2) | ((uint32_t)__half_as_ushort(h3) << 16);
    return r;
}

// ───────────── pre-pass: x fp32 -> swizzled fp16 tiles ─────────────
__global__ void __launch_bounds__(THREADS)
cvt_x_kernel(const float* __restrict__ x) {
    const int i = blockIdx.x;    // 0..63
    const int ch = blockIdx.y;   // 0..31
    unsigned char* tile = g_xh + ((size_t)i * NCHUNK + ch) * TILE_A;
    const float* src = x + (size_t)i * KDIM + ch * KC;
#pragma unroll
    for (int it = 0; it < 4; ++it) {
        int f = threadIdx.x + it * THREADS;   // float4 idx 0..1023
        int b = f >> 3;
        int c4 = f & 7;
        const float4 v = *reinterpret_cast<const float4*>(
            src + (size_t)b * (IDIM * KDIM) + c4 * 4);
        *reinterpret_cast<uint2*>(tile + SWZ64(b * 64 + c4 * 8)) = pack_hi4(v);
    }
}

// ───────────── main GEMM ─────────────

// cp.async one A fp16 tile (8 KB, already swizzled) into smem.
static __device__ __forceinline__ void stage_a(uint32_t dst,
                                               const unsigned char* tile) {
#pragma unroll
    for (int it = 0; it < 2; ++it) {
        int g = threadIdx.x + it * THREADS;   // 16B granule, 0..511
        cp16(dst + (uint32_t)(g * 16), tile + (size_t)g * 16);
    }
}

// cp.async one B fp32 chunk [128 x 32] into a stage (self-consumed layout).
static __device__ __forceinline__ void stage_b(uint32_t stg,
                                               const float* __restrict__ gb) {
#pragma unroll
    for (int it = 0; it < 4; ++it) {
        int f = threadIdx.x + it * THREADS;   // float4 idx 0..1023
        int row = f >> 3;
        int c4 = f & 7;
        cp16(stg + (uint32_t)(f * 16), gb + (size_t)row * 65536 + c4 * 4);
    }
}

// Convert own staged B fp32 -> swizzled fp16 tile.
static __device__ __forceinline__ void convert_b(char* sm, uint32_t stg_off,
                                                 uint32_t dst_off) {
#pragma unroll
    for (int it = 0; it < 4; ++it) {
        int f = threadIdx.x + it * THREADS;
        int row = f >> 3;
        int c4 = f & 7;
        const float4 v = *reinterpret_cast<const float4*>(sm + stg_off + f * 16);
        *reinterpret_cast<uint2*>(sm + dst_off + SWZ64(row * 64 + c4 * 8)) =
            pack_hi4(v);
    }
}

__global__ void __launch_bounds__(THREADS, 2)
fl_kernel(const float* __restrict__ w, const float* __restrict__ bias,
          float* __restrict__ out) {
    extern __shared__ char sm[];
    const uint32_t sbase = smem_u32(sm);
    const int tid = threadIdx.x;
    const int wid = tid >> 5;
    const int lid = tid & 31;
    const int warp_m = wid >> 2;   // 0..1 : 64 M rows each
    const int warp_n = wid & 3;    // 0..3 : 32 N cols each
    const int otile = blockIdx.x;  // 0..7
    const int i_idx = blockIdx.y;  // 0..63

    const unsigned char* xtiles = g_xh + (size_t)i_idx * NCHUNK * TILE_A;
    const float* wa = w + ((size_t)otile * 128) * (IDIM * KDIM) + (size_t)i_idx * KDIM;

    float acc[4][4][4];
#pragma unroll
    for (int a = 0; a < 4; ++a)
#pragma unroll
        for (int b = 0; b < 4; ++b)
#pragma unroll
            for (int c = 0; c < 4; ++c) acc[a][b][c] = 0.0f;

    const uint32_t a_row = (uint32_t)(warp_m * 64 + (lid & 15));
    const uint32_t a_cb = (uint32_t)((lid >> 4) * 16);
    const uint32_t b_row = (uint32_t)(warp_n * 32 + ((lid >> 4) << 3) + (lid & 7));
    const uint32_t b_cb = (uint32_t)(((lid >> 3) & 1) * 16);

    // Prologue: stage chunks 0 and 1 (groups 0, 1); convert chunk 0.
    stage_a(sbase + OFF_A + 0 * TILE_A, xtiles);
    stage_b(sbase + OFF_STG + 0 * BSTG_SZ, wa);
    asm volatile("cp.async.commit_group;" ::: "memory");
    stage_a(sbase + OFF_A + 1 * TILE_A, xtiles + TILE_A);
    stage_b(sbase + OFF_STG + 1 * BSTG_SZ, wa + KC);
    asm volatile("cp.async.commit_group;" ::: "memory");
    asm volatile("cp.async.wait_group 1;" ::: "memory");
    convert_b(sm, OFF_STG + 0 * BSTG_SZ, OFF_B16 + 0 * TILE_B16);
    __syncthreads();

    int a_slot = 0;   // A buffer index of current chunk (mod 3)
    for (int ch = 0; ch < NCHUNK; ++ch) {
        const int a_next2 = (a_slot + 2 >= 3) ? (a_slot - 1) : (a_slot + 2);
        const bool pf = (ch + 2 < NCHUNK);

        // Prefetch chunk ch+2 (group ch+2). Bstg[(ch+2)&1] == Bstg[ch&1] was
        // self-consumed by this thread's convert at the previous iteration.
        if (pf) {
            stage_a(sbase + OFF_A + (uint32_t)(a_next2 * TILE_A),
                    xtiles + (size_t)(ch + 2) * TILE_A);
            stage_b(sbase + OFF_STG + (uint32_t)((ch & 1) * BSTG_SZ),
                    wa + (ch + 2) * KC);
            asm volatile("cp.async.commit_group;" ::: "memory");
        }

        // MMA on A[a_slot], B16[ch&1]: 2 K=16 steps
        const uint32_t abuf = sbase + OFF_A + (uint32_t)(a_slot * TILE_A);
        const uint32_t bbuf = sbase + OFF_B16 + (uint32_t)((ch & 1) * TILE_B16);
#pragma unroll
        for (int ks = 0; ks < 2; ++ks) {
            uint32_t ah[4][4], bh[2][4];
#pragma unroll
            for (int mt = 0; mt < 4; ++mt)
                ldm_x4(ah[mt], abuf +
                       SWZ64((a_row + mt * 16) * 64 + ks * 32 + a_cb));
#pragma unroll
            for (int bt = 0; bt < 2; ++bt)
                ldm_x4(bh[bt], bbuf +
                       SWZ64((b_row + bt * 16) * 64 + ks * 32 + b_cb));
#pragma unroll
            for (int mt = 0; mt < 4; ++mt)
#pragma unroll
                for (int nt = 0; nt < 4; ++nt)
                    mma_f16(acc[mt][nt], ah[mt], &bh[nt >> 1][(nt & 1) * 2]);
        }

        // Ensure chunk ch+1 landed (one group may stay in flight), convert it.
        if (pf) {
            asm volatile("cp.async.wait_group 1;" ::: "memory");
        } else {
            asm volatile("cp.async.wait_group 0;" ::: "memory");
        }
        if (ch + 1 < NCHUNK) {
            convert_b(sm, OFF_STG + (uint32_t)(((ch + 1) & 1) * BSTG_SZ),
                      OFF_B16 + (uint32_t)(((ch + 1) & 1) * TILE_B16));
        }
        __syncthreads();

        a_slot = (a_slot + 1 >= 3) ? 0 : (a_slot + 1);
    }

    // Epilogue: add bias, store. out[b][o][i] = b*65536 + o*64 + i
    const float* bp = bias + (size_t)(otile * 128) * IDIM + i_idx;
    float bv[4][2];
#pragma unroll
    for (int nt = 0; nt < 4; ++nt) {
        int n_l = warp_n * 32 + nt * 8 + 2 * (lid & 3);
        bv[nt][0] = bp[(size_t)n_l * IDIM];
        bv[nt][1] = bp[(size_t)(n_l + 1) * IDIM];
    }
#pragma unroll
    for (int mt = 0; mt < 4; ++mt) {
        int m0 = warp_m * 64 + mt * 16 + (lid >> 2);
#pragma unroll
        for (int nt = 0; nt < 4; ++nt) {
            int n_l = warp_n * 32 + nt * 8 + 2 * (lid & 3);
            float* o0 = out + (size_t)m0 * (ODIM * IDIM) +
                        (size_t)(otile * 128 + n_l) * IDIM + i_idx;
            o0[0] = acc[mt][nt][0] + bv[nt][0];
            o0[IDIM] = acc[mt][nt][1] + bv[nt][1];
            float* o8 = o0 + (size_t)8 * (ODIM * IDIM);
            o8[0] = acc[mt][nt][2] + bv[nt][0];
            o8[IDIM] = acc[mt][nt][3] + bv[nt][1];
        }
    }
}

extern "C" void kernel_launch(void* const* d_in, const int* in_sizes, int n_in,
                              void* d_out, int out_size) {
    (void)in_sizes; (void)n_in; (void)out_size;
    const float* x = (const float*)d_in[0];
    const float* w = (const float*)d_in[1];
    const float* bias = (const float*)d_in[2];
    float* out = (float*)d_out;

    cvt_x_kernel<<<dim3(IDIM, NCHUNK), THREADS>>>(x);

    cudaFuncSetAttribute(fl_kernel, cudaFuncAttributeMaxDynamicSharedMemorySize,
                         SMEM_DYN);
    fl_kernel<<<dim3(ODIM / 128, IDIM), THREADS, SMEM_DYN>>>(w, bias, out);
}